// round 1
// baseline (speedup 1.0000x reference)
#include <cuda_runtime.h>
#include <cuda_bf16.h>
#include <cstdint>

// interpolation1D: NE elements, element e = (e, e+1).
//   c0 = nodes[e], c1 = nodes[e+1]
//   x_g = 0.5*c0 + 0.5*c1
//   det_im = c0 - c1 ; n0 = (x_g - c1)/det_im ; n1 = (c0 - x_g)/det_im
//   detJ = (c1 - c0)
//   vals[0] = imposed[0], vals[N-1] = imposed[1], vals[i] = free_vals[i-1] otherwise
//   u = vals[e]*n0 + vals[e+1]*n1
// Outputs concatenated in d_out: u[0:NE], x_g[NE:2NE], detJ[2NE:3NE]

__global__ void interp1d_kernel(const float* __restrict__ nodes,
                                const float* __restrict__ free_vals,
                                const float* __restrict__ imposed_vals,
                                float* __restrict__ out_u,
                                float* __restrict__ out_xg,
                                float* __restrict__ out_detJ,
                                int ne)  // ne divisible by 4
{
    int t = blockIdx.x * blockDim.x + threadIdx.x;
    int e0 = t * 4;
    if (e0 >= ne) return;

    // nodes[e0 .. e0+4] : float4 + 1 scalar (e0+4 <= ne, nodes has ne+1 entries)
    float4 nd = *reinterpret_cast<const float4*>(nodes + e0);
    float  nd4 = nodes[e0 + 4];

    // vals for node indices e0..e0+4:
    //   vals[i] = free_vals[i-1]  (i in 1..ne-1), vals[0]=imposed[0], vals[ne]=imposed[1]
    // v0[lane k] = vals[e0+k], v1[lane k] = vals[e0+k+1]
    float4 fv = *reinterpret_cast<const float4*>(free_vals + e0); // free_vals[e0..e0+3] = vals[e0+1..e0+4]*
    float  vprev = (e0 == 0) ? imposed_vals[0] : free_vals[e0 - 1];   // vals[e0]
    float  vlast = fv.w;
    if (e0 + 4 == ne) vlast = imposed_vals[1];                        // vals[ne] dirichlet

    float c0[4] = {nd.x, nd.y, nd.z, nd.w};
    float c1[4] = {nd.y, nd.z, nd.w, nd4};
    float v0[4] = {vprev, fv.x, fv.y, fv.z};
    float v1[4] = {fv.x, fv.y, fv.z, vlast};

    float4 ru, rx, rd;
    float* pu = &ru.x; float* px = &rx.x; float* pd = &rd.x;

    #pragma unroll
    for (int k = 0; k < 4; k++) {
        float xg     = 0.5f * c0[k] + 0.5f * c1[k];
        float det_im = c0[k] - c1[k];
        float inv    = 1.0f / det_im;
        float n0     = (xg - c1[k]) * inv;
        float n1     = (c0[k] - xg) * inv;
        pu[k] = v0[k] * n0 + v1[k] * n1;
        px[k] = xg;
        pd[k] = c1[k] - c0[k];   // * w_g (=1.0)
    }

    *reinterpret_cast<float4*>(out_u    + e0) = ru;
    *reinterpret_cast<float4*>(out_xg   + e0) = rx;
    *reinterpret_cast<float4*>(out_detJ + e0) = rd;
}

extern "C" void kernel_launch(void* const* d_in, const int* in_sizes, int n_in,
                              void* d_out, int out_size)
{
    // metadata order: nodes, free_vals, imposed_vals, elements, free_idx, dirichlet
    const float* nodes    = (const float*)d_in[0];
    const float* freevals = (const float*)d_in[1];
    const float* imposed  = (const float*)d_in[2];
    // elements / free_idx / dirichlet are structurally deterministic (e, e+1), ignored.

    int ne = in_sizes[0] - 1;           // N_NODES - 1 = 2^24
    float* out = (float*)d_out;
    float* out_u    = out;
    float* out_xg   = out + ne;
    float* out_detJ = out + 2 * (size_t)ne;

    int nthreads = ne / 4;
    int tpb = 256;
    int blocks = (nthreads + tpb - 1) / tpb;
    interp1d_kernel<<<blocks, tpb>>>(nodes, freevals, imposed,
                                     out_u, out_xg, out_detJ, ne);
}

// round 2
// speedup vs baseline: 1.0048x; 1.0048x over previous
#include <cuda_runtime.h>
#include <cuda_bf16.h>
#include <cstdint>

// interpolation1D: NE elements, element e = (e, e+1).
//   c0 = nodes[e], c1 = nodes[e+1]
//   x_g = 0.5*c0 + 0.5*c1
//   det_im = c0 - c1 ; inv = 1/det_im
//   n0 = (x_g - c1)*inv ; n1 = (c0 - x_g)*inv
//   detJ = (c1 - c0)
//   vals[0]=imposed[0], vals[NE]=imposed[1], vals[i]=free_vals[i-1] otherwise
//   u = vals[e]*n0 + vals[e+1]*n1
// Outputs concatenated in d_out: u[0:NE], x_g[NE:2NE], detJ[2NE:3NE]
//
// 8 elements per thread. Halo values (nodes[e0+8], free_vals[e0-1]) come from
// neighbor lanes via warp shuffle; only warp-edge lanes do a scalar load.

__global__ void __launch_bounds__(256) interp1d_kernel(
        const float* __restrict__ nodes,
        const float* __restrict__ free_vals,
        const float* __restrict__ imposed_vals,
        float* __restrict__ out_u,
        float* __restrict__ out_xg,
        float* __restrict__ out_detJ,
        int ne)   // ne divisible by 8*256
{
    int t  = blockIdx.x * blockDim.x + threadIdx.x;
    long e0 = (long)t * 8;
    if (e0 >= ne) return;
    int lane = threadIdx.x & 31;

    // front-batched vector loads (streaming: touch-once data)
    float4 a = __ldcs(reinterpret_cast<const float4*>(nodes + e0));
    float4 b = __ldcs(reinterpret_cast<const float4*>(nodes + e0 + 4));
    float4 p = __ldcs(reinterpret_cast<const float4*>(free_vals + e0));
    float4 q = __ldcs(reinterpret_cast<const float4*>(free_vals + e0 + 4));

    // halo: nodes[e0+8] = next lane's a.x ; free_vals[e0-1] = prev lane's q.w
    float nd8   = __shfl_down_sync(0xFFFFFFFFu, a.x, 1);
    float vprev = __shfl_up_sync  (0xFFFFFFFFu, q.w, 1);
    if (lane == 31) nd8   = nodes[e0 + 8];              // nodes has ne+1 entries
    if (lane == 0)  vprev = (e0 == 0) ? imposed_vals[0] : free_vals[e0 - 1];
    float vlast = q.w;
    if (e0 + 8 == ne) vlast = imposed_vals[1];          // dirichlet at node ne

    // node coords c[0..8] and nodal values v[0..8] for nodes e0..e0+8
    float c[9] = {a.x, a.y, a.z, a.w, b.x, b.y, b.z, b.w, nd8};
    float v[9] = {vprev, p.x, p.y, p.z, p.w, q.x, q.y, q.z, vlast};

    float u[8], xg[8], dj[8];
    #pragma unroll
    for (int k = 0; k < 8; k++) {
        float c0 = c[k], c1 = c[k + 1];
        float x      = 0.5f * c0 + 0.5f * c1;
        float det_im = c0 - c1;
        float inv    = 1.0f / det_im;
        float n0     = (x - c1) * inv;
        float n1     = (c0 - x) * inv;
        u[k]  = v[k] * n0 + v[k + 1] * n1;
        xg[k] = x;
        dj[k] = c1 - c0;   // * w_g (=1.0)
    }

    float4 r;
    r = make_float4(u[0], u[1], u[2], u[3]);
    __stcs(reinterpret_cast<float4*>(out_u + e0), r);
    r = make_float4(u[4], u[5], u[6], u[7]);
    __stcs(reinterpret_cast<float4*>(out_u + e0 + 4), r);
    r = make_float4(xg[0], xg[1], xg[2], xg[3]);
    __stcs(reinterpret_cast<float4*>(out_xg + e0), r);
    r = make_float4(xg[4], xg[5], xg[6], xg[7]);
    __stcs(reinterpret_cast<float4*>(out_xg + e0 + 4), r);
    r = make_float4(dj[0], dj[1], dj[2], dj[3]);
    __stcs(reinterpret_cast<float4*>(out_detJ + e0), r);
    r = make_float4(dj[4], dj[5], dj[6], dj[7]);
    __stcs(reinterpret_cast<float4*>(out_detJ + e0 + 4), r);
}

extern "C" void kernel_launch(void* const* d_in, const int* in_sizes, int n_in,
                              void* d_out, int out_size)
{
    // metadata order: nodes, free_vals, imposed_vals, elements, free_idx, dirichlet
    const float* nodes    = (const float*)d_in[0];
    const float* freevals = (const float*)d_in[1];
    const float* imposed  = (const float*)d_in[2];
    // elements / free_idx / dirichlet are structurally deterministic (e, e+1), ignored.

    int ne = in_sizes[0] - 1;           // N_NODES - 1 = 2^24
    float* out = (float*)d_out;
    float* out_u    = out;
    float* out_xg   = out + ne;
    float* out_detJ = out + 2 * (size_t)ne;

    int nthreads = ne / 8;              // 2^21
    int tpb = 256;
    int blocks = (nthreads + tpb - 1) / tpb;
    interp1d_kernel<<<blocks, tpb>>>(nodes, freevals, imposed,
                                     out_u, out_xg, out_detJ, ne);
}